// round 4
// baseline (speedup 1.0000x reference)
#include <cuda_runtime.h>

// Problem constants
constexpr int BATCH = 32;
constexpr int HEADS = 128;
constexpr int KD    = 128;   // head_dim
constexpr int RD    = 512;   // lora rank
constexpr int LSEQ  = 4096;  // kv length
constexpr int DQ    = 1536;  // q lora rank
constexpr int HK    = HEADS * KD;  // 16384

// Scratch (allocation-free: __device__ globals)
__device__ float g_q[BATCH * HK];                    //  2 MB
__device__ float g_qabs[BATCH * HEADS * RD];         //  8 MB
__device__ float g_scores[(size_t)BATCH * HEADS * LSEQ]; // 64 MB
__device__ float g_ctx[BATCH * HEADS * RD];          //  8 MB

// ---------------------------------------------------------------------------
// Generic tiled fp32 GEMM.
//   C[z] = A[z] (BM x Kd, row-major lda) * op(B[z]) (+bias)
//   BT=true : B is (N x Kd) row-major ldb  -> C = A * B^T   (both K-contiguous)
//   BT=false: B is (Kd x N) row-major ldb  -> C = A * B
//   M == BM always (single M tile). grid.x covers N, grid.y covers batch z.
// Smem layout transposed ([BK][dim]) so fragment loads are vectorized float4.
// ---------------------------------------------------------------------------
template <int BM, int BN, int BK, int TM, int TN, bool BT, bool BIAS>
__global__ __launch_bounds__((BM / TM) * (BN / TN))
void gemm_kernel(const float* __restrict__ A, const float* __restrict__ Bm,
                 const float* __restrict__ bias, float* __restrict__ C,
                 int Kd, int lda, int ldb, int ldc,
                 long sA, long sB, long sC) {
    constexpr int TX = BN / TN;
    constexpr int TY = BM / TM;
    constexpr int NTHREADS = TX * TY;

    __shared__ __align__(16) float As[BK][BM];
    __shared__ __align__(16) float Bs[BK][BN];

    const int tid = threadIdx.x;
    const int tx = tid % TX;
    const int ty = tid / TX;
    const int m0 = ty * TM;
    const int n0 = tx * TN;
    const int n0g = blockIdx.x * BN;
    const long z = blockIdx.y;

    A  += z * sA;
    Bm += z * sB;
    C  += z * sC;

    float acc[TM][TN];
#pragma unroll
    for (int i = 0; i < TM; i++)
#pragma unroll
        for (int j = 0; j < TN; j++) acc[i][j] = 0.f;

    constexpr int KV = BK / 4;  // float4 per k-row

    for (int k0 = 0; k0 < Kd; k0 += BK) {
        // --- load A tile (BM x BK), k-contiguous float4, scatter-transpose ---
#pragma unroll
        for (int idx = tid; idx < BM * KV; idx += NTHREADS) {
            int m  = idx / KV;
            int k4 = idx % KV;
            float4 v = *reinterpret_cast<const float4*>(A + (long)m * lda + k0 + 4 * k4);
            As[4 * k4 + 0][m] = v.x;
            As[4 * k4 + 1][m] = v.y;
            As[4 * k4 + 2][m] = v.z;
            As[4 * k4 + 3][m] = v.w;
        }
        // --- load B tile ---
        if (BT) {
#pragma unroll
            for (int idx = tid; idx < BN * KV; idx += NTHREADS) {
                int n  = idx / KV;
                int k4 = idx % KV;
                float4 v = *reinterpret_cast<const float4*>(
                    Bm + (long)(n0g + n) * ldb + k0 + 4 * k4);
                Bs[4 * k4 + 0][n] = v.x;
                Bs[4 * k4 + 1][n] = v.y;
                Bs[4 * k4 + 2][n] = v.z;
                Bs[4 * k4 + 3][n] = v.w;
            }
        } else {
            constexpr int NV = BN / 4;
#pragma unroll
            for (int idx = tid; idx < BK * NV; idx += NTHREADS) {
                int k  = idx / NV;
                int n4 = idx % NV;
                float4 v = *reinterpret_cast<const float4*>(
                    Bm + (long)(k0 + k) * ldb + n0g + 4 * n4);
                *reinterpret_cast<float4*>(&Bs[k][4 * n4]) = v;
            }
        }
        __syncthreads();

#pragma unroll
        for (int kk = 0; kk < BK; kk++) {
            float ar[TM], br[TN];
#pragma unroll
            for (int i = 0; i < TM; i += 4) {
                float4 v = *reinterpret_cast<const float4*>(&As[kk][m0 + i]);
                ar[i] = v.x; ar[i + 1] = v.y; ar[i + 2] = v.z; ar[i + 3] = v.w;
            }
#pragma unroll
            for (int j = 0; j < TN; j += 4) {
                float4 v = *reinterpret_cast<const float4*>(&Bs[kk][n0 + j]);
                br[j] = v.x; br[j + 1] = v.y; br[j + 2] = v.z; br[j + 3] = v.w;
            }
#pragma unroll
            for (int i = 0; i < TM; i++)
#pragma unroll
                for (int j = 0; j < TN; j++)
                    acc[i][j] = fmaf(ar[i], br[j], acc[i][j]);
        }
        __syncthreads();
    }

    // --- store (vectorized) ---
#pragma unroll
    for (int i = 0; i < TM; i++) {
#pragma unroll
        for (int j = 0; j < TN; j += 4) {
            float4 v;
            v.x = acc[i][j + 0];
            v.y = acc[i][j + 1];
            v.z = acc[i][j + 2];
            v.w = acc[i][j + 3];
            if (BIAS) {
                v.x += bias[n0g + n0 + j + 0];
                v.y += bias[n0g + n0 + j + 1];
                v.z += bias[n0g + n0 + j + 2];
                v.w += bias[n0g + n0 + j + 3];
            }
            *reinterpret_cast<float4*>(C + (long)(m0 + i) * ldc + n0g + n0 + j) = v;
        }
    }
}

// ---------------------------------------------------------------------------
// Row softmax over L=4096, one CTA (256 threads) per row, values in registers.
// ---------------------------------------------------------------------------
__global__ __launch_bounds__(256) void softmax_kernel(float* __restrict__ S) {
    const long row = blockIdx.x;
    float* p = S + row * (long)LSEQ;
    const int t = threadIdx.x;

    float v[16];
    float m = -3.4e38f;
#pragma unroll
    for (int i = 0; i < 16; i++) {
        v[i] = p[t + (i << 8)];
        m = fmaxf(m, v[i]);
    }

    __shared__ float rmax[8], rsum[8];
#pragma unroll
    for (int o = 16; o > 0; o >>= 1) m = fmaxf(m, __shfl_xor_sync(0xffffffffu, m, o));
    if ((t & 31) == 0) rmax[t >> 5] = m;
    __syncthreads();
#pragma unroll
    for (int i = 0; i < 8; i++) m = fmaxf(m, rmax[i]);

    float s = 0.f;
#pragma unroll
    for (int i = 0; i < 16; i++) {
        v[i] = __expf(v[i] - m);
        s += v[i];
    }
#pragma unroll
    for (int o = 16; o > 0; o >>= 1) s += __shfl_xor_sync(0xffffffffu, s, o);
    if ((t & 31) == 0) rsum[t >> 5] = s;
    __syncthreads();
    s = 0.f;
#pragma unroll
    for (int i = 0; i < 8; i++) s += rsum[i];

    const float inv = 1.f / s;
#pragma unroll
    for (int i = 0; i < 16; i++) p[t + (i << 8)] = v[i] * inv;
}

// ---------------------------------------------------------------------------
// Launch pipeline.
// Inputs (metadata order): hidden_states_q[B,DQ], compressed_kv[B,L,R],
//                          Wq[HK,DQ], bq[HK], w_kc[H,K,R], w_vc[H,K,R]
// Output: [B, HK] fp32
// ---------------------------------------------------------------------------
extern "C" void kernel_launch(void* const* d_in, const int* in_sizes, int n_in,
                              void* d_out, int out_size) {
    (void)in_sizes; (void)n_in; (void)out_size;
    const float* hs  = (const float*)d_in[0];
    const float* kv  = (const float*)d_in[1];
    const float* Wq  = (const float*)d_in[2];
    const float* bq  = (const float*)d_in[3];
    const float* wkc = (const float*)d_in[4];
    const float* wvc = (const float*)d_in[5];
    float* out = (float*)d_out;

    float *q, *qabs, *sc, *ctx;
    cudaGetSymbolAddress((void**)&q,    g_q);
    cudaGetSymbolAddress((void**)&qabs, g_qabs);
    cudaGetSymbolAddress((void**)&sc,   g_scores);
    cudaGetSymbolAddress((void**)&ctx,  g_ctx);

    // 1) q = hs @ Wq^T + bq : [32, 16384], K=1536 (NT)
    gemm_kernel<32, 128, 32, 4, 8, true, true><<<dim3(HK / 128, 1), 128>>>(
        hs, Wq, bq, q, DQ, DQ, DQ, HK, 0, 0, 0);

    // 2) q_abs[b,h,r] = sum_k q[b,h,k] * w_kc[h,k,r] : per-head [32,512], K=128 (NN)
    gemm_kernel<32, 128, 16, 4, 8, false, false><<<dim3(RD / 128, HEADS), 128>>>(
        q, wkc, nullptr, qabs, KD, HK, RD, HEADS * RD,
        (long)KD, (long)KD * RD, (long)RD);

    // 3) scores[b,h,l] = sum_r q_abs[b,h,r] * kv[b,l,r] : per-batch [128,4096], K=512 (NT)
    gemm_kernel<128, 128, 16, 8, 8, true, false><<<dim3(LSEQ / 128, BATCH), 256>>>(
        qabs, kv, nullptr, sc, RD, RD, RD, LSEQ,
        (long)HEADS * RD, (long)LSEQ * RD, (long)HEADS * LSEQ);

    // 4) softmax over l
    softmax_kernel<<<BATCH * HEADS, 256>>>(sc);

    // 5) ctx[b,h,r] = sum_l probs[b,h,l] * kv[b,l,r] : per-batch [128,512], K=4096 (NN)
    gemm_kernel<128, 64, 16, 8, 8, false, false><<<dim3(RD / 64, BATCH), 128>>>(
        sc, kv, nullptr, ctx, LSEQ, LSEQ, RD, RD,
        (long)HEADS * LSEQ, (long)LSEQ * RD, (long)HEADS * RD);

    // 6) out[b,h,k] = sum_r ctx[b,h,r] * w_vc[h,k,r] : per-head [32,128], K=512 (NT)
    gemm_kernel<32, 128, 16, 4, 8, true, false><<<dim3(1, HEADS), 128>>>(
        ctx, wvc, nullptr, out, RD, HEADS * RD, RD, HK,
        (long)RD, (long)KD * RD, (long)KD);
}

// round 8
// speedup vs baseline: 2.9775x; 2.9775x over previous
#include <cuda_runtime.h>
#include <cuda_bf16.h>
#include <cstdint>

// Problem constants
constexpr int BATCH = 32;
constexpr int HEADS = 128;
constexpr int KD    = 128;   // head_dim
constexpr int RD    = 512;   // lora rank
constexpr int LSEQ  = 4096;  // kv length
constexpr int DQ    = 1536;  // q lora rank
constexpr int HK    = HEADS * KD;  // 16384

// Scratch (allocation-free: __device__ globals; 256B-aligned for cp.async/uint4)
__device__ __align__(256) float g_q[BATCH * HK];                        //  2 MB
__device__ __align__(256) float g_qabs[BATCH * HEADS * RD];             //  8 MB
__device__ __align__(256) float g_scores[(size_t)BATCH * HEADS * LSEQ]; // 64 MB
__device__ __align__(256) float g_ctx[BATCH * HEADS * RD];              //  8 MB
__device__ __align__(256) float g_ctx_part[2][BATCH * HEADS * RD];      // 16 MB
__device__ __align__(256) __nv_bfloat16 g_qabs_hi[BATCH * HEADS * RD];  //  4 MB
__device__ __align__(256) __nv_bfloat16 g_qabs_lo[BATCH * HEADS * RD];  //  4 MB
__device__ __align__(256) __nv_bfloat16 g_kv_hi[(size_t)BATCH * LSEQ * RD];   // 128 MB
__device__ __align__(256) __nv_bfloat16 g_kv_lo[(size_t)BATCH * LSEQ * RD];   // 128 MB
__device__ __align__(256) __nv_bfloat16 g_kvT_hi[(size_t)BATCH * RD * LSEQ];  // 128 MB
__device__ __align__(256) __nv_bfloat16 g_kvT_lo[(size_t)BATCH * RD * LSEQ];  // 128 MB
__device__ __align__(256) __nv_bfloat16 g_probs_hi[(size_t)BATCH * HEADS * LSEQ]; // 32 MB
__device__ __align__(256) __nv_bfloat16 g_probs_lo[(size_t)BATCH * HEADS * LSEQ]; // 32 MB

// ===========================================================================
// Helpers (all non-'a' PTX: cp.async / ldmatrix / mma.sync — legal on sm_103)
// ===========================================================================
__device__ __forceinline__ uint32_t smem_u32(const void* p) {
    uint32_t a;
    asm("{ .reg .u64 t; cvta.to.shared.u64 t, %1; cvt.u32.u64 %0, t; }"
        : "=r"(a) : "l"(p));
    return a;
}
__device__ __forceinline__ void cp16(uint32_t dst, const void* src) {
    asm volatile("cp.async.cg.shared.global [%0], [%1], 16;" :: "r"(dst), "l"(src));
}
__device__ __forceinline__ void cp_commit() {
    asm volatile("cp.async.commit_group;" ::: "memory");
}
template <int N> __device__ __forceinline__ void cp_wait() {
    asm volatile("cp.async.wait_group %0;" :: "n"(N) : "memory");
}
__device__ __forceinline__ void ldsm4(uint32_t* r, uint32_t addr) {
    asm volatile("ldmatrix.sync.aligned.m8n8.x4.shared.b16 {%0,%1,%2,%3}, [%4];"
                 : "=r"(r[0]), "=r"(r[1]), "=r"(r[2]), "=r"(r[3]) : "r"(addr));
}
__device__ __forceinline__ void mma_bf16(float* d, const uint32_t* a, const uint32_t* b) {
    asm volatile(
        "mma.sync.aligned.m16n8k16.row.col.f32.bf16.bf16.f32 "
        "{%0,%1,%2,%3}, {%4,%5,%6,%7}, {%8,%9}, {%0,%1,%2,%3};"
        : "+f"(d[0]), "+f"(d[1]), "+f"(d[2]), "+f"(d[3])
        : "r"(a[0]), "r"(a[1]), "r"(a[2]), "r"(a[3]), "r"(b[0]), "r"(b[1]));
}
__device__ __forceinline__ void split1(float x, __nv_bfloat16& h, __nv_bfloat16& l) {
    h = __float2bfloat16(x);
    l = __float2bfloat16(x - __bfloat162float(h));
}
__device__ __forceinline__ uint32_t pack2(__nv_bfloat16 a, __nv_bfloat16 b) {
    return (uint32_t)__bfloat16_as_ushort(a) |
           ((uint32_t)__bfloat16_as_ushort(b) << 16);
}

// ===========================================================================
// bf16x3 split HMMA GEMM.
//   C[z] (128 x 128*gridDim.x) = Ah*Bh + Ah*Bl + Al*Bh  (fp32 accum)
//   A: [128][K] K-major bf16 hi/lo, ldA.   B: [N][K] K-major bf16 hi/lo, ldB.
//   grid: (n_tiles, z, ksplit).  blockIdx.z offsets k by z*Klen and C by sCpart.
//   2-stage cp.async pipeline, K-chunk 64, smem 2 x 64KB.
// Tiles stored SW128-swizzled (off ^= (off>>3)&0x70); served to both A and B
// fragments via non-trans ldmatrix (K-major [N][K] == col-major KxN for row.col).
// ===========================================================================
constexpr int STAGE_BYTES = 65536;
constexpr int T_AH = 0, T_AL = 16384, T_BH = 32768, T_BL = 49152;
constexpr int MMA_SMEM = 2 * STAGE_BYTES;

__device__ __forceinline__ void prefetch_tile(uint32_t sbase,
                                              const __nv_bfloat16* __restrict__ src,
                                              long ld, int tid) {
#pragma unroll
    for (int t = 0; t < 4; t++) {
        int idx = tid + t * 256;
        int r = idx >> 3, u = idx & 7;
        uint32_t off = (uint32_t)(r * 128 + u * 16);
        uint32_t sw = off ^ ((off >> 3) & 0x70);
        cp16(sbase + sw, src + (size_t)r * ld + u * 8);
    }
}

__global__ __launch_bounds__(256) void mma_bf16x3_kernel(
    const __nv_bfloat16* __restrict__ Ah, const __nv_bfloat16* __restrict__ Al,
    const __nv_bfloat16* __restrict__ Bh, const __nv_bfloat16* __restrict__ Bl,
    float* __restrict__ C, int Klen, long ldA, long ldB, long ldC,
    long sAz, long sBz, long sCz, long sCpart) {
    extern __shared__ __align__(16) char smem[];
    const int tid = threadIdx.x;
    const int wid = tid >> 5, lane = tid & 31;
    const long z = blockIdx.y;
    const long kOff = (long)blockIdx.z * Klen;
    const long nOff = (long)blockIdx.x * 128;

    Ah += z * sAz + kOff;
    Al += z * sAz + kOff;
    Bh += z * sBz + nOff * ldB + kOff;
    Bl += z * sBz + nOff * ldB + kOff;
    C  += z * sCz + (long)blockIdx.z * sCpart + nOff;

    const uint32_t sb = smem_u32(smem);
    const int nch = Klen >> 6;
    const int mW = (wid >> 2) * 64;
    const int nW = (wid & 3) * 32;

    float acc[4][4][4];
#pragma unroll
    for (int i = 0; i < 4; i++)
#pragma unroll
        for (int j = 0; j < 4; j++)
#pragma unroll
            for (int k = 0; k < 4; k++) acc[i][j][k] = 0.f;

    // prologue: prefetch chunk 0 into stage 0
    prefetch_tile(sb + T_AH, Ah, ldA, tid);
    prefetch_tile(sb + T_AL, Al, ldA, tid);
    prefetch_tile(sb + T_BH, Bh, ldB, tid);
    prefetch_tile(sb + T_BL, Bl, ldB, tid);
    cp_commit();

    for (int kc = 0; kc < nch; kc++) {
        if (kc + 1 < nch) {
            uint32_t s = sb + ((kc + 1) & 1) * STAGE_BYTES;
            long ko = (long)(kc + 1) * 64;
            prefetch_tile(s + T_AH, Ah + ko, ldA, tid);
            prefetch_tile(s + T_AL, Al + ko, ldA, tid);
            prefetch_tile(s + T_BH, Bh + ko, ldB, tid);
            prefetch_tile(s + T_BL, Bl + ko, ldB, tid);
            cp_commit();
            cp_wait<1>();
        } else {
            cp_wait<0>();
        }
        __syncthreads();

        const uint32_t st = sb + (kc & 1) * STAGE_BYTES;
#pragma unroll
        for (int ks = 0; ks < 4; ks++) {
            uint32_t ah[4][4], al[4][4], bh[2][4], bl[2][4];
            // A fragments: 4 m16 tiles, hi and lo
#pragma unroll
            for (int mt = 0; mt < 4; mt++) {
                uint32_t off = (uint32_t)((mW + mt * 16 + (lane & 15)) * 128 +
                                          ks * 32 + (lane >> 4) * 16);
                uint32_t sw = off ^ ((off >> 3) & 0x70);
                ldsm4(ah[mt], st + T_AH + sw);
                ldsm4(al[mt], st + T_AL + sw);
            }
            // B fragments: 2 x4-loads cover 4 n8 tiles, hi and lo
#pragma unroll
            for (int bp = 0; bp < 2; bp++) {
                uint32_t row = (uint32_t)(nW + bp * 16 + ((lane >> 4) << 3) + (lane & 7));
                uint32_t off = row * 128 + ks * 32 + ((lane >> 3) & 1) * 16;
                uint32_t sw = off ^ ((off >> 3) & 0x70);
                ldsm4(bh[bp], st + T_BH + sw);
                ldsm4(bl[bp], st + T_BL + sw);
            }
            // combo 1: Ah*Bh  (RAW distance 16 per acc)
#pragma unroll
            for (int mt = 0; mt < 4; mt++)
#pragma unroll
                for (int nt = 0; nt < 4; nt++)
                    mma_bf16(acc[mt][nt], ah[mt], &bh[nt >> 1][(nt & 1) * 2]);
            // combo 2: Ah*Bl
#pragma unroll
            for (int mt = 0; mt < 4; mt++)
#pragma unroll
                for (int nt = 0; nt < 4; nt++)
                    mma_bf16(acc[mt][nt], ah[mt], &bl[nt >> 1][(nt & 1) * 2]);
            // combo 3: Al*Bh
#pragma unroll
            for (int mt = 0; mt < 4; mt++)
#pragma unroll
                for (int nt = 0; nt < 4; nt++)
                    mma_bf16(acc[mt][nt], al[mt], &bh[nt >> 1][(nt & 1) * 2]);
        }
        __syncthreads();
    }

    // epilogue: direct fp32 stores (d0,d1)/(d2,d3) are n-adjacent pairs
    const int mrow = mW + (lane >> 2);
    const int ncol = nW + 2 * (lane & 3);
#pragma unroll
    for (int mt = 0; mt < 4; mt++)
#pragma unroll
        for (int nt = 0; nt < 4; nt++) {
            float2 v0 = make_float2(acc[mt][nt][0], acc[mt][nt][1]);
            float2 v1 = make_float2(acc[mt][nt][2], acc[mt][nt][3]);
            *reinterpret_cast<float2*>(C + (size_t)(mrow + mt * 16) * ldC + ncol + nt * 8) = v0;
            *reinterpret_cast<float2*>(C + (size_t)(mrow + mt * 16 + 8) * ldC + ncol + nt * 8) = v1;
        }
}

// ===========================================================================
// kv prep: kv[b][l][r] fp32 -> straight hi/lo bf16 AND transposed hi/lo bf16
// ===========================================================================
__global__ __launch_bounds__(128) void kv_split_kernel(
    const float* __restrict__ kv,
    __nv_bfloat16* __restrict__ sh, __nv_bfloat16* __restrict__ sl,
    __nv_bfloat16* __restrict__ th, __nv_bfloat16* __restrict__ tl) {
    __shared__ float s[64 * 67];
    const int l0 = blockIdx.x * 64, r0 = blockIdx.y * 64, b = blockIdx.z;
    const int tid = threadIdx.x;
    const float* src = kv + ((size_t)b * LSEQ + l0) * RD + r0;
#pragma unroll
    for (int t = 0; t < 8; t++) {
        int idx = tid + t * 128;
        int i = idx >> 4, j4 = idx & 15;
        float4 v = *reinterpret_cast<const float4*>(src + (size_t)i * RD + 4 * j4);
        s[i * 67 + 4 * j4 + 0] = v.x;
        s[i * 67 + 4 * j4 + 1] = v.y;
        s[i * 67 + 4 * j4 + 2] = v.z;
        s[i * 67 + 4 * j4 + 3] = v.w;
        __nv_bfloat16 h0, h1, h2, h3, q0, q1, q2, q3;
        split1(v.x, h0, q0); split1(v.y, h1, q1);
        split1(v.z, h2, q2); split1(v.w, h3, q3);
        size_t o = ((size_t)b * LSEQ + l0 + i) * RD + r0 + 4 * j4;
        uint2 ph; ph.x = pack2(h0, h1); ph.y = pack2(h2, h3);
        uint2 pl; pl.x = pack2(q0, q1); pl.y = pack2(q2, q3);
        *reinterpret_cast<uint2*>(sh + o) = ph;
        *reinterpret_cast<uint2*>(sl + o) = pl;
    }
    __syncthreads();
    const size_t obase = ((size_t)b * RD + r0) * LSEQ + l0;
#pragma unroll
    for (int t = 0; t < 8; t++) {
        int idx = tid + t * 128;
        int r = idx >> 4, q = idx & 15;
        float x0 = s[(4 * q + 0) * 67 + r];
        float x1 = s[(4 * q + 1) * 67 + r];
        float x2 = s[(4 * q + 2) * 67 + r];
        float x3 = s[(4 * q + 3) * 67 + r];
        __nv_bfloat16 h0, h1, h2, h3, q0, q1, q2, q3;
        split1(x0, h0, q0); split1(x1, h1, q1);
        split1(x2, h2, q2); split1(x3, h3, q3);
        uint2 ph; ph.x = pack2(h0, h1); ph.y = pack2(h2, h3);
        uint2 pl; pl.x = pack2(q0, q1); pl.y = pack2(q2, q3);
        *reinterpret_cast<uint2*>(th + obase + (size_t)r * LSEQ + 4 * q) = ph;
        *reinterpret_cast<uint2*>(tl + obase + (size_t)r * LSEQ + 4 * q) = pl;
    }
}

// Elementwise fp32 -> hi/lo bf16 split (for qabs)
__global__ __launch_bounds__(256) void split_kernel(
    const float4* __restrict__ in, uint2* __restrict__ hi, uint2* __restrict__ lo) {
    int i = blockIdx.x * 256 + threadIdx.x;
    float4 v = in[i];
    __nv_bfloat16 h0, h1, h2, h3, q0, q1, q2, q3;
    split1(v.x, h0, q0); split1(v.y, h1, q1);
    split1(v.z, h2, q2); split1(v.w, h3, q3);
    uint2 ph; ph.x = pack2(h0, h1); ph.y = pack2(h2, h3);
    uint2 pl; pl.x = pack2(q0, q1); pl.y = pack2(q2, q3);
    hi[i] = ph;
    lo[i] = pl;
}

// ===========================================================================
// Row softmax over L=4096; emits probs directly as hi/lo bf16.
// ===========================================================================
__global__ __launch_bounds__(256) void softmax_split_kernel(
    const float* __restrict__ S, __nv_bfloat16* __restrict__ ph,
    __nv_bfloat16* __restrict__ pl) {
    const size_t row = blockIdx.x;
    const float* p = S + row * (size_t)LSEQ;
    const int t = threadIdx.x;

    float v[16];
    float m = -3.4e38f;
#pragma unroll
    for (int i = 0; i < 16; i++) {
        v[i] = p[t + (i << 8)];
        m = fmaxf(m, v[i]);
    }

    __shared__ float rmax[8], rsum[8];
#pragma unroll
    for (int o = 16; o > 0; o >>= 1) m = fmaxf(m, __shfl_xor_sync(0xffffffffu, m, o));
    if ((t & 31) == 0) rmax[t >> 5] = m;
    __syncthreads();
#pragma unroll
    for (int i = 0; i < 8; i++) m = fmaxf(m, rmax[i]);

    float s = 0.f;
#pragma unroll
    for (int i = 0; i < 16; i++) {
        v[i] = __expf(v[i] - m);
        s += v[i];
    }
#pragma unroll
    for (int o = 16; o > 0; o >>= 1) s += __shfl_xor_sync(0xffffffffu, s, o);
    if ((t & 31) == 0) rsum[t >> 5] = s;
    __syncthreads();
    s = 0.f;
#pragma unroll
    for (int i = 0; i < 8; i++) s += rsum[i];

    const float inv = 1.f / s;
    __nv_bfloat16* oh = ph + row * (size_t)LSEQ;
    __nv_bfloat16* ol = pl + row * (size_t)LSEQ;
#pragma unroll
    for (int i = 0; i < 16; i++) {
        float x = v[i] * inv;
        __nv_bfloat16 h, l;
        split1(x, h, l);
        oh[t + (i << 8)] = h;
        ol[t + (i << 8)] = l;
    }
}

// Sum the two split-K partials (deterministic).
__global__ __launch_bounds__(256) void reduce_ctx(const float4* __restrict__ p0,
                                                  const float4* __restrict__ p1,
                                                  float4* __restrict__ c) {
    int i = blockIdx.x * 256 + threadIdx.x;
    float4 a = p0[i], b = p1[i];
    a.x += b.x; a.y += b.y; a.z += b.z; a.w += b.w;
    c[i] = a;
}

// ===========================================================================
// Generic tiled fp32 GEMM (small steps 1, 2, 6)
// ===========================================================================
template <int BM, int BN, int BK, int TM, int TN, bool BT, bool BIAS>
__global__ __launch_bounds__((BM / TM) * (BN / TN))
void gemm_kernel(const float* __restrict__ A, const float* __restrict__ Bm,
                 const float* __restrict__ bias, float* __restrict__ C,
                 int Kd, int lda, int ldb, int ldc,
                 long sA, long sB, long sC) {
    constexpr int TX = BN / TN;
    constexpr int TY = BM / TM;
    constexpr int NTHREADS = TX * TY;

    __shared__ __align__(16) float As[BK][BM];
    __shared__ __align__(16) float Bs[BK][BN];

    const int tid = threadIdx.x;
    const int tx = tid % TX;
    const int ty = tid / TX;
    const int m0 = ty * TM;
    const int n0 = tx * TN;
    const int n0g = blockIdx.x * BN;
    const long z = blockIdx.y;

    A += z * sA; Bm += z * sB; C += z * sC;

    float acc[TM][TN];
#pragma unroll
    for (int i = 0; i < TM; i++)
#pragma unroll
        for (int j = 0; j < TN; j++) acc[i][j] = 0.f;

    constexpr int KV = BK / 4;

    for (int k0 = 0; k0 < Kd; k0 += BK) {
#pragma unroll
        for (int idx = tid; idx < BM * KV; idx += NTHREADS) {
            int m = idx / KV, k4 = idx % KV;
            float4 v = *reinterpret_cast<const float4*>(A + (long)m * lda + k0 + 4 * k4);
            As[4 * k4 + 0][m] = v.x; As[4 * k4 + 1][m] = v.y;
            As[4 * k4 + 2][m] = v.z; As[4 * k4 + 3][m] = v.w;
        }
        if (BT) {
#pragma unroll
            for (int idx = tid; idx < BN * KV; idx += NTHREADS) {
                int n = idx / KV, k4 = idx % KV;
                float4 v = *reinterpret_cast<const float4*>(
                    Bm + (long)(n0g + n) * ldb + k0 + 4 * k4);
                Bs[4 * k4 + 0][n] = v.x; Bs[4 * k4 + 1][n] = v.y;
                Bs[4 * k4 + 2][n] = v.z; Bs[4 * k4 + 3][n] = v.w;
            }
        } else {
            constexpr int NV = BN / 4;
#pragma unroll
            for (int idx = tid; idx < BK * NV; idx += NTHREADS) {
                int k = idx / NV, n4 = idx % NV;
                float4 v = *reinterpret_cast<const float4*>(
                    Bm + (long)(k0 + k) * ldb + n0g + 4 * n4);
                *reinterpret_cast<float4*>(&Bs[k][4 * n4]) = v;
            }
        }
        __syncthreads();

#pragma unroll
        for (int kk = 0; kk < BK; kk++) {
            float ar[TM], br[TN];
#pragma unroll
            for (int i = 0; i < TM; i += 4) {
                float4 v = *reinterpret_cast<const float4*>(&As[kk][m0 + i]);
                ar[i] = v.x; ar[i + 1] = v.y; ar[i + 2] = v.z; ar[i + 3] = v.w;
            }
#pragma unroll
            for (int j = 0; j < TN; j += 4) {
                float4 v = *reinterpret_cast<const float4*>(&Bs[kk][n0 + j]);
                br[j] = v.x; br[j + 1] = v.y; br[j + 2] = v.z; br[j + 3] = v.w;
            }
#pragma unroll
            for (int i = 0; i < TM; i++)
#pragma unroll
                for (int j = 0; j < TN; j++)
                    acc[i][j] = fmaf(ar[i], br[j], acc[i][j]);
        }
        __syncthreads();
    }

#pragma unroll
    for (int i = 0; i < TM; i++) {
#pragma unroll
        for (int j = 0; j < TN; j += 4) {
            float4 v;
            v.x = acc[i][j + 0]; v.y = acc[i][j + 1];
            v.z = acc[i][j + 2]; v.w = acc[i][j + 3];
            if (BIAS) {
                v.x += bias[n0g + n0 + j + 0];
                v.y += bias[n0g + n0 + j + 1];
                v.z += bias[n0g + n0 + j + 2];
                v.w += bias[n0g + n0 + j + 3];
            }
            *reinterpret_cast<float4*>(C + (long)(m0 + i) * ldc + n0g + n0 + j) = v;
        }
    }
}

// ===========================================================================
// Launch pipeline
// ===========================================================================
extern "C" void kernel_launch(void* const* d_in, const int* in_sizes, int n_in,
                              void* d_out, int out_size) {
    (void)in_sizes; (void)n_in; (void)out_size;
    const float* hs  = (const float*)d_in[0];
    const float* kv  = (const float*)d_in[1];
    const float* Wq  = (const float*)d_in[2];
    const float* bq  = (const float*)d_in[3];
    const float* wkc = (const float*)d_in[4];
    const float* wvc = (const float*)d_in[5];
    float* out = (float*)d_out;

    float *q, *qabs, *sc, *ctx, *part;
    __nv_bfloat16 *qh, *ql, *kvh, *kvl, *kvTh, *kvTl, *prh, *prl;
    cudaGetSymbolAddress((void**)&q,    g_q);
    cudaGetSymbolAddress((void**)&qabs, g_qabs);
    cudaGetSymbolAddress((void**)&sc,   g_scores);
    cudaGetSymbolAddress((void**)&ctx,  g_ctx);
    cudaGetSymbolAddress((void**)&part, g_ctx_part);
    cudaGetSymbolAddress((void**)&qh,   g_qabs_hi);
    cudaGetSymbolAddress((void**)&ql,   g_qabs_lo);
    cudaGetSymbolAddress((void**)&kvh,  g_kv_hi);
    cudaGetSymbolAddress((void**)&kvl,  g_kv_lo);
    cudaGetSymbolAddress((void**)&kvTh, g_kvT_hi);
    cudaGetSymbolAddress((void**)&kvTl, g_kvT_lo);
    cudaGetSymbolAddress((void**)&prh,  g_probs_hi);
    cudaGetSymbolAddress((void**)&prl,  g_probs_lo);

    cudaFuncSetAttribute(mma_bf16x3_kernel,
                         cudaFuncAttributeMaxDynamicSharedMemorySize, MMA_SMEM);

    // 0) kv -> straight + transposed hi/lo bf16
    kv_split_kernel<<<dim3(LSEQ / 64, RD / 64, BATCH), 128>>>(kv, kvh, kvl, kvTh, kvTl);

    // 1) q = hs @ Wq^T + bq (fp32)
    gemm_kernel<32, 128, 32, 4, 8, true, true><<<dim3(HK / 128, 1), 128>>>(
        hs, Wq, bq, q, DQ, DQ, DQ, HK, 0, 0, 0);

    // 2) q_abs[b,h,r] = sum_k q[b,h,k] * w_kc[h,k,r] (fp32)
    gemm_kernel<32, 128, 16, 4, 8, false, false><<<dim3(RD / 128, HEADS), 128>>>(
        q, wkc, nullptr, qabs, KD, HK, RD, HEADS * RD,
        (long)KD, (long)KD * RD, (long)RD);

    // 2b) qabs -> hi/lo bf16
    split_kernel<<<(BATCH * HEADS * RD) / (4 * 256), 256>>>(
        (const float4*)qabs, (uint2*)qh, (uint2*)ql);

    // 3) scores = qabs @ kv^T via HMMA bf16x3: grid (l-tiles, batch)
    mma_bf16x3_kernel<<<dim3(LSEQ / 128, BATCH, 1), 256, MMA_SMEM>>>(
        qh, ql, kvh, kvl, sc, RD,
        (long)RD, (long)RD, (long)LSEQ,
        (long)HEADS * RD, (long)LSEQ * RD, (long)HEADS * LSEQ, 0);

    // 4) softmax -> probs hi/lo bf16
    softmax_split_kernel<<<BATCH * HEADS, 256>>>(sc, prh, prl);

    // 5) ctx = probs @ kvT^T via HMMA bf16x3, split-K x2: grid (r-tiles, batch, 2)
    mma_bf16x3_kernel<<<dim3(RD / 128, BATCH, 2), 256, MMA_SMEM>>>(
        prh, prl, kvTh, kvTl, part, LSEQ / 2,
        (long)LSEQ, (long)LSEQ, (long)RD,
        (long)HEADS * LSEQ, (long)RD * LSEQ, (long)HEADS * RD,
        (long)BATCH * HEADS * RD);
    reduce_ctx<<<(BATCH * HEADS * RD) / (256 * 4), 256>>>(
        (const float4*)part, (const float4*)(part + BATCH * HEADS * RD), (float4*)ctx);

    // 6) out[b,h,k] = sum_r ctx[b,h,r] * w_vc[h,k,r] (fp32)
    gemm_kernel<32, 128, 16, 4, 8, true, false><<<dim3(1, HEADS), 128>>>(
        ctx, wvc, nullptr, out, RD, HEADS * RD, RD, HK,
        (long)RD, (long)KD * RD, (long)KD);
}

// round 14
// speedup vs baseline: 3.5724x; 1.1998x over previous
#include <cuda_runtime.h>
#include <cuda_bf16.h>
#include <cstdint>

// Problem constants
constexpr int BATCH = 32;
constexpr int HEADS = 128;
constexpr int KD    = 128;   // head_dim
constexpr int RD    = 512;   // lora rank
constexpr int LSEQ  = 4096;  // kv length
constexpr int DQ    = 1536;  // q lora rank
constexpr int HK    = HEADS * KD;  // 16384

// Scratch (allocation-free: __device__ globals; 256B-aligned for cp.async/uint4)
__device__ __align__(256) float g_q[BATCH * HK];                        //  2 MB
__device__ __align__(256) float g_qabs[BATCH * HEADS * RD];             //  8 MB
__device__ __align__(256) float g_scores[(size_t)BATCH * HEADS * LSEQ]; // 64 MB
__device__ __align__(256) float g_ctx[BATCH * HEADS * RD];              //  8 MB
__device__ __align__(256) float g_ctx_part[2][BATCH * HEADS * RD];      // 16 MB
__device__ __align__(256) __nv_bfloat16 g_qabs_hi[BATCH * HEADS * RD];  //  4 MB
__device__ __align__(256) __nv_bfloat16 g_qabs_lo[BATCH * HEADS * RD];  //  4 MB
__device__ __align__(256) __nv_bfloat16 g_kv_hi[(size_t)BATCH * LSEQ * RD];   // 128 MB
__device__ __align__(256) __nv_bfloat16 g_kv_lo[(size_t)BATCH * LSEQ * RD];   // 128 MB
__device__ __align__(256) __nv_bfloat16 g_probs_hi[(size_t)BATCH * HEADS * LSEQ]; // 32 MB
__device__ __align__(256) __nv_bfloat16 g_probs_lo[(size_t)BATCH * HEADS * LSEQ]; // 32 MB

// ===========================================================================
// Helpers (all non-'a' PTX: cp.async / ldmatrix / mma.sync — legal on sm_103)
// ===========================================================================
__device__ __forceinline__ uint32_t smem_u32(const void* p) {
    uint32_t a;
    asm("{ .reg .u64 t; cvta.to.shared.u64 t, %1; cvt.u32.u64 %0, t; }"
        : "=r"(a) : "l"(p));
    return a;
}
__device__ __forceinline__ void cp16(uint32_t dst, const void* src) {
    asm volatile("cp.async.cg.shared.global [%0], [%1], 16;" :: "r"(dst), "l"(src));
}
__device__ __forceinline__ void cp_commit() {
    asm volatile("cp.async.commit_group;" ::: "memory");
}
template <int N> __device__ __forceinline__ void cp_wait() {
    asm volatile("cp.async.wait_group %0;" :: "n"(N) : "memory");
}
__device__ __forceinline__ void ldsm4(uint32_t* r, uint32_t addr) {
    asm volatile("ldmatrix.sync.aligned.m8n8.x4.shared.b16 {%0,%1,%2,%3}, [%4];"
                 : "=r"(r[0]), "=r"(r[1]), "=r"(r[2]), "=r"(r[3]) : "r"(addr));
}
__device__ __forceinline__ void ldsm4t(uint32_t* r, uint32_t addr) {
    asm volatile("ldmatrix.sync.aligned.m8n8.x4.trans.shared.b16 {%0,%1,%2,%3}, [%4];"
                 : "=r"(r[0]), "=r"(r[1]), "=r"(r[2]), "=r"(r[3]) : "r"(addr));
}
__device__ __forceinline__ void mma_bf16(float* d, const uint32_t* a, const uint32_t* b) {
    asm volatile(
        "mma.sync.aligned.m16n8k16.row.col.f32.bf16.bf16.f32 "
        "{%0,%1,%2,%3}, {%4,%5,%6,%7}, {%8,%9}, {%0,%1,%2,%3};"
        : "+f"(d[0]), "+f"(d[1]), "+f"(d[2]), "+f"(d[3])
        : "r"(a[0]), "r"(a[1]), "r"(a[2]), "r"(a[3]), "r"(b[0]), "r"(b[1]));
}
__device__ __forceinline__ void split1(float x, __nv_bfloat16& h, __nv_bfloat16& l) {
    h = __float2bfloat16(x);
    l = __float2bfloat16(x - __bfloat162float(h));
}
__device__ __forceinline__ uint32_t pack2(__nv_bfloat16 a, __nv_bfloat16 b) {
    return (uint32_t)__bfloat16_as_ushort(a) |
           ((uint32_t)__bfloat16_as_ushort(b) << 16);
}

// ===========================================================================
// bf16x3 split HMMA GEMM.
//   C[z] (128 x 128*gridDim.x) = Ah*Bh + Ah*Bl + Al*Bh  (fp32 accum)
//   A: [128][K] K-major bf16 hi/lo, ldA.
//   TRANSB=false: B is [N][K] K-major, ldB (row = n).   (scores: B = kv rows l)
//   TRANSB=true : B is [K][N] N-major, ldB (row = k).   (ctx:    B = kv rows l, n = r)
//   grid: (n_tiles, z, ksplit).  blockIdx.z offsets k by z*Klen and C by sCpart.
//   2-stage cp.async pipeline, K-chunk 64, smem 2 x 64KB.
// K-major tiles: 128 rows x 128B, SW128 swizzle, non-trans ldmatrix.
// N-major tiles: 64 rows x 256B, col16 ^= (row&7) swizzle, trans ldmatrix.
// ===========================================================================
constexpr int STAGE_BYTES = 65536;
constexpr int T_AH = 0, T_AL = 16384, T_BH = 32768, T_BL = 49152;
constexpr int MMA_SMEM = 2 * STAGE_BYTES;

// K-major tile prefetch: 128 rows x 64 bf16 (128B), SW128 swizzle.
__device__ __forceinline__ void prefetch_tile(uint32_t sbase,
                                              const __nv_bfloat16* __restrict__ src,
                                              long ld, int tid) {
#pragma unroll
    for (int t = 0; t < 4; t++) {
        int idx = tid + t * 256;
        int r = idx >> 3, u = idx & 7;
        uint32_t off = (uint32_t)(r * 128 + u * 16);
        uint32_t sw = off ^ ((off >> 3) & 0x70);
        cp16(sbase + sw, src + (size_t)r * ld + u * 8);
    }
}
// N-major tile prefetch: 64 k-rows x 128 bf16 (256B), col16 ^= (row&7).
__device__ __forceinline__ void prefetch_tile_t(uint32_t sbase,
                                                const __nv_bfloat16* __restrict__ src,
                                                long ld, int tid) {
#pragma unroll
    for (int t = 0; t < 4; t++) {
        int idx = tid + t * 256;
        int r = idx >> 4, c = idx & 15;
        uint32_t sw = (uint32_t)(r * 256 + ((c ^ (r & 7)) << 4));
        cp16(sbase + sw, src + (size_t)r * ld + c * 8);
    }
}

template <bool TRANSB>
__global__ __launch_bounds__(256) void mma_bf16x3_kernel(
    const __nv_bfloat16* __restrict__ Ah, const __nv_bfloat16* __restrict__ Al,
    const __nv_bfloat16* __restrict__ Bh, const __nv_bfloat16* __restrict__ Bl,
    float* __restrict__ C, int Klen, long ldA, long ldB, long ldC,
    long sAz, long sBz, long sCz, long sCpart) {
    extern __shared__ __align__(16) char smem[];
    const int tid = threadIdx.x;
    const int wid = tid >> 5, lane = tid & 31;
    const long z = blockIdx.y;
    const long kOff = (long)blockIdx.z * Klen;
    const long nOff = (long)blockIdx.x * 128;

    Ah += z * sAz + kOff;
    Al += z * sAz + kOff;
    if (TRANSB) {
        Bh += z * sBz + kOff * ldB + nOff;
        Bl += z * sBz + kOff * ldB + nOff;
    } else {
        Bh += z * sBz + nOff * ldB + kOff;
        Bl += z * sBz + nOff * ldB + kOff;
    }
    C += z * sCz + (long)blockIdx.z * sCpart + nOff;

    const long kstep = TRANSB ? 64 * ldB : 64;  // B advance per chunk
    const uint32_t sb = smem_u32(smem);
    const int nch = Klen >> 6;
    const int mW = (wid >> 2) * 64;
    const int nW = (wid & 3) * 32;

    float acc[4][4][4];
#pragma unroll
    for (int i = 0; i < 4; i++)
#pragma unroll
        for (int j = 0; j < 4; j++)
#pragma unroll
            for (int k = 0; k < 4; k++) acc[i][j][k] = 0.f;

    // prologue: prefetch chunk 0 into stage 0
    prefetch_tile(sb + T_AH, Ah, ldA, tid);
    prefetch_tile(sb + T_AL, Al, ldA, tid);
    if (TRANSB) {
        prefetch_tile_t(sb + T_BH, Bh, ldB, tid);
        prefetch_tile_t(sb + T_BL, Bl, ldB, tid);
    } else {
        prefetch_tile(sb + T_BH, Bh, ldB, tid);
        prefetch_tile(sb + T_BL, Bl, ldB, tid);
    }
    cp_commit();

    for (int kc = 0; kc < nch; kc++) {
        if (kc + 1 < nch) {
            uint32_t s = sb + ((kc + 1) & 1) * STAGE_BYTES;
            long ko = (long)(kc + 1) * 64;
            prefetch_tile(s + T_AH, Ah + ko, ldA, tid);
            prefetch_tile(s + T_AL, Al + ko, ldA, tid);
            if (TRANSB) {
                prefetch_tile_t(s + T_BH, Bh + (long)(kc + 1) * kstep, ldB, tid);
                prefetch_tile_t(s + T_BL, Bl + (long)(kc + 1) * kstep, ldB, tid);
            } else {
                prefetch_tile(s + T_BH, Bh + (long)(kc + 1) * kstep, ldB, tid);
                prefetch_tile(s + T_BL, Bl + (long)(kc + 1) * kstep, ldB, tid);
            }
            cp_commit();
            cp_wait<1>();
        } else {
            cp_wait<0>();
        }
        __syncthreads();

        const uint32_t st = sb + (kc & 1) * STAGE_BYTES;
#pragma unroll
        for (int ks = 0; ks < 4; ks++) {
            uint32_t ah[4][4], al[4][4], bh[2][4], bl[2][4];
            // A fragments: 4 m16 tiles, hi and lo (K-major, non-trans)
#pragma unroll
            for (int mt = 0; mt < 4; mt++) {
                uint32_t off = (uint32_t)((mW + mt * 16 + (lane & 15)) * 128 +
                                          ks * 32 + (lane >> 4) * 16);
                uint32_t sw = off ^ ((off >> 3) & 0x70);
                ldsm4(ah[mt], st + T_AH + sw);
                ldsm4(al[mt], st + T_AL + sw);
            }
            // B fragments
            if (TRANSB) {
                // [K][N] tile, 256B pitch: trans ldmatrix.
                // m0: k0-7 @ n0-7, m1: k8-15 @ n0-7, m2: k0-7 @ n8-15, m3: k8-15 @ n8-15
#pragma unroll
                for (int bp = 0; bp < 2; bp++) {
                    uint32_t r_ = (uint32_t)(ks * 16 + ((lane >> 3) & 1) * 8 + (lane & 7));
                    uint32_t c16 = (uint32_t)((nW + bp * 16 + (lane >> 4) * 8) >> 3);
                    uint32_t addr = r_ * 256 + ((c16 ^ (r_ & 7)) << 4);
                    ldsm4t(bh[bp], st + T_BH + addr);
                    ldsm4t(bl[bp], st + T_BL + addr);
                }
            } else {
                // [N][K] tile, 128B pitch: non-trans ldmatrix.
#pragma unroll
                for (int bp = 0; bp < 2; bp++) {
                    uint32_t row = (uint32_t)(nW + bp * 16 + ((lane >> 4) << 3) + (lane & 7));
                    uint32_t off = row * 128 + ks * 32 + ((lane >> 3) & 1) * 16;
                    uint32_t sw = off ^ ((off >> 3) & 0x70);
                    ldsm4(bh[bp], st + T_BH + sw);
                    ldsm4(bl[bp], st + T_BL + sw);
                }
            }
            // combo 1: Ah*Bh  (RAW distance 16 per acc)
#pragma unroll
            for (int mt = 0; mt < 4; mt++)
#pragma unroll
                for (int nt = 0; nt < 4; nt++)
                    mma_bf16(acc[mt][nt], ah[mt], &bh[nt >> 1][(nt & 1) * 2]);
            // combo 2: Ah*Bl
#pragma unroll
            for (int mt = 0; mt < 4; mt++)
#pragma unroll
                for (int nt = 0; nt < 4; nt++)
                    mma_bf16(acc[mt][nt], ah[mt], &bl[nt >> 1][(nt & 1) * 2]);
            // combo 3: Al*Bh
#pragma unroll
            for (int mt = 0; mt < 4; mt++)
#pragma unroll
                for (int nt = 0; nt < 4; nt++)
                    mma_bf16(acc[mt][nt], al[mt], &bh[nt >> 1][(nt & 1) * 2]);
        }
        __syncthreads();
    }

    // epilogue: direct fp32 stores (d0,d1)/(d2,d3) are n-adjacent pairs
    const int mrow = mW + (lane >> 2);
    const int ncol = nW + 2 * (lane & 3);
#pragma unroll
    for (int mt = 0; mt < 4; mt++)
#pragma unroll
        for (int nt = 0; nt < 4; nt++) {
            float2 v0 = make_float2(acc[mt][nt][0], acc[mt][nt][1]);
            float2 v1 = make_float2(acc[mt][nt][2], acc[mt][nt][3]);
            *reinterpret_cast<float2*>(C + (size_t)(mrow + mt * 16) * ldC + ncol + nt * 8) = v0;
            *reinterpret_cast<float2*>(C + (size_t)(mrow + mt * 16 + 8) * ldC + ncol + nt * 8) = v1;
        }
}

// ===========================================================================
// kv prep: pure elementwise fp32 -> hi/lo bf16 (no transpose needed).
// 8 floats per thread, fully coalesced uint4 I/O.
// ===========================================================================
__global__ __launch_bounds__(256) void kv_split_kernel(
    const float4* __restrict__ kv, uint4* __restrict__ hi, uint4* __restrict__ lo) {
    size_t i = (size_t)blockIdx.x * 256 + threadIdx.x;
    float4 a = kv[2 * i], b = kv[2 * i + 1];
    __nv_bfloat16 h[8], l[8];
    split1(a.x, h[0], l[0]); split1(a.y, h[1], l[1]);
    split1(a.z, h[2], l[2]); split1(a.w, h[3], l[3]);
    split1(b.x, h[4], l[4]); split1(b.y, h[5], l[5]);
    split1(b.z, h[6], l[6]); split1(b.w, h[7], l[7]);
    uint4 ph, pl;
    ph.x = pack2(h[0], h[1]); ph.y = pack2(h[2], h[3]);
    ph.z = pack2(h[4], h[5]); ph.w = pack2(h[6], h[7]);
    pl.x = pack2(l[0], l[1]); pl.y = pack2(l[2], l[3]);
    pl.z = pack2(l[4], l[5]); pl.w = pack2(l[6], l[7]);
    hi[i] = ph;
    lo[i] = pl;
}

// Elementwise fp32 -> hi/lo bf16 split (for qabs)
__global__ __launch_bounds__(256) void split_kernel(
    const float4* __restrict__ in, uint2* __restrict__ hi, uint2* __restrict__ lo) {
    int i = blockIdx.x * 256 + threadIdx.x;
    float4 v = in[i];
    __nv_bfloat16 h0, h1, h2, h3, q0, q1, q2, q3;
    split1(v.x, h0, q0); split1(v.y, h1, q1);
    split1(v.z, h2, q2); split1(v.w, h3, q3);
    uint2 ph; ph.x = pack2(h0, h1); ph.y = pack2(h2, h3);
    uint2 pl; pl.x = pack2(q0, q1); pl.y = pack2(q2, q3);
    hi[i] = ph;
    lo[i] = pl;
}

// ===========================================================================
// Row softmax over L=4096; emits probs directly as hi/lo bf16.
// ===========================================================================
__global__ __launch_bounds__(256) void softmax_split_kernel(
    const float* __restrict__ S, __nv_bfloat16* __restrict__ ph,
    __nv_bfloat16* __restrict__ pl) {
    const size_t row = blockIdx.x;
    const float* p = S + row * (size_t)LSEQ;
    const int t = threadIdx.x;

    float v[16];
    float m = -3.4e38f;
#pragma unroll
    for (int i = 0; i < 16; i++) {
        v[i] = p[t + (i << 8)];
        m = fmaxf(m, v[i]);
    }

    __shared__ float rmax[8], rsum[8];
#pragma unroll
    for (int o = 16; o > 0; o >>= 1) m = fmaxf(m, __shfl_xor_sync(0xffffffffu, m, o));
    if ((t & 31) == 0) rmax[t >> 5] = m;
    __syncthreads();
#pragma unroll
    for (int i = 0; i < 8; i++) m = fmaxf(m, rmax[i]);

    float s = 0.f;
#pragma unroll
    for (int i = 0; i < 16; i++) {
        v[i] = __expf(v[i] - m);
        s += v[i];
    }
#pragma unroll
    for (int o = 16; o > 0; o >>= 1) s += __shfl_xor_sync(0xffffffffu, s, o);
    if ((t & 31) == 0) rsum[t >> 5] = s;
    __syncthreads();
    s = 0.f;
#pragma unroll
    for (int i = 0; i < 8; i++) s += rsum[i];

    const float inv = 1.f / s;
    __nv_bfloat16* oh = ph + row * (size_t)LSEQ;
    __nv_bfloat16* ol = pl + row * (size_t)LSEQ;
#pragma unroll
    for (int i = 0; i < 16; i++) {
        float x = v[i] * inv;
        __nv_bfloat16 h, l;
        split1(x, h, l);
        oh[t + (i << 8)] = h;
        ol[t + (i << 8)] = l;
    }
}

// Sum the two split-K partials (deterministic).
__global__ __launch_bounds__(256) void reduce_ctx(const float4* __restrict__ p0,
                                                  const float4* __restrict__ p1,
                                                  float4* __restrict__ c) {
    int i = blockIdx.x * 256 + threadIdx.x;
    float4 a = p0[i], b = p1[i];
    a.x += b.x; a.y += b.y; a.z += b.z; a.w += b.w;
    c[i] = a;
}

// ===========================================================================
// Generic tiled fp32 GEMM (small steps 1, 2, 6)
// ===========================================================================
template <int BM, int BN, int BK, int TM, int TN, bool BT, bool BIAS>
__global__ __launch_bounds__((BM / TM) * (BN / TN))
void gemm_kernel(const float* __restrict__ A, const float* __restrict__ Bm,
                 const float* __restrict__ bias, float* __restrict__ C,
                 int Kd, int lda, int ldb, int ldc,
                 long sA, long sB, long sC) {
    constexpr int TX = BN / TN;
    constexpr int TY = BM / TM;
    constexpr int NTHREADS = TX * TY;

    __shared__ __align__(16) float As[BK][BM];
    __shared__ __align__(16) float Bs[BK][BN];

    const int tid = threadIdx.x;
    const int tx = tid % TX;
    const int ty = tid / TX;
    const int m0 = ty * TM;
    const int n0 = tx * TN;
    const int n0g = blockIdx.x * BN;
    const long z = blockIdx.y;

    A += z * sA; Bm += z * sB; C += z * sC;

    float acc[TM][TN];
#pragma unroll
    for (int i = 0; i < TM; i++)
#pragma unroll
        for (int j = 0; j < TN; j++) acc[i][j] = 0.f;

    constexpr int KV = BK / 4;

    for (int k0 = 0; k0 < Kd; k0 += BK) {
#pragma unroll
        for (int idx = tid; idx < BM * KV; idx += NTHREADS) {
            int m = idx / KV, k4 = idx % KV;
            float4 v = *reinterpret_cast<const float4*>(A + (long)m * lda + k0 + 4 * k4);
            As[4 * k4 + 0][m] = v.x; As[4 * k4 + 1][m] = v.y;
            As[4 * k4 + 2][m] = v.z; As[4 * k4 + 3][m] = v.w;
        }
        if (BT) {
#pragma unroll
            for (int idx = tid; idx < BN * KV; idx += NTHREADS) {
                int n = idx / KV, k4 = idx % KV;
                float4 v = *reinterpret_cast<const float4*>(
                    Bm + (long)(n0g + n) * ldb + k0 + 4 * k4);
                Bs[4 * k4 + 0][n] = v.x; Bs[4 * k4 + 1][n] = v.y;
                Bs[4 * k4 + 2][n] = v.z; Bs[4 * k4 + 3][n] = v.w;
            }
        } else {
            constexpr int NV = BN / 4;
#pragma unroll
            for (int idx = tid; idx < BK * NV; idx += NTHREADS) {
                int k = idx / NV, n4 = idx % NV;
                float4 v = *reinterpret_cast<const float4*>(
                    Bm + (long)(k0 + k) * ldb + n0g + 4 * n4);
                *reinterpret_cast<float4*>(&Bs[k][4 * n4]) = v;
            }
        }
        __syncthreads();

#pragma unroll
        for (int kk = 0; kk < BK; kk++) {
            float ar[TM], br[TN];
#pragma unroll
            for (int i = 0; i < TM; i += 4) {
                float4 v = *reinterpret_cast<const float4*>(&As[kk][m0 + i]);
                ar[i] = v.x; ar[i + 1] = v.y; ar[i + 2] = v.z; ar[i + 3] = v.w;
            }
#pragma unroll
            for (int j = 0; j < TN; j += 4) {
                float4 v = *reinterpret_cast<const float4*>(&Bs[kk][n0 + j]);
                br[j] = v.x; br[j + 1] = v.y; br[j + 2] = v.z; br[j + 3] = v.w;
            }
#pragma unroll
            for (int i = 0; i < TM; i++)
#pragma unroll
                for (int j = 0; j < TN; j++)
                    acc[i][j] = fmaf(ar[i], br[j], acc[i][j]);
        }
        __syncthreads();
    }

#pragma unroll
    for (int i = 0; i < TM; i++) {
#pragma unroll
        for (int j = 0; j < TN; j += 4) {
            float4 v;
            v.x = acc[i][j + 0]; v.y = acc[i][j + 1];
            v.z = acc[i][j + 2]; v.w = acc[i][j + 3];
            if (BIAS) {
                v.x += bias[n0g + n0 + j + 0];
                v.y += bias[n0g + n0 + j + 1];
                v.z += bias[n0g + n0 + j + 2];
                v.w += bias[n0g + n0 + j + 3];
            }
            *reinterpret_cast<float4*>(C + (long)(m0 + i) * ldc + n0g + n0 + j) = v;
        }
    }
}

// ===========================================================================
// Launch pipeline
// ===========================================================================
extern "C" void kernel_launch(void* const* d_in, const int* in_sizes, int n_in,
                              void* d_out, int out_size) {
    (void)in_sizes; (void)n_in; (void)out_size;
    const float* hs  = (const float*)d_in[0];
    const float* kv  = (const float*)d_in[1];
    const float* Wq  = (const float*)d_in[2];
    const float* bq  = (const float*)d_in[3];
    const float* wkc = (const float*)d_in[4];
    const float* wvc = (const float*)d_in[5];
    float* out = (float*)d_out;

    float *q, *qabs, *sc, *ctx, *part;
    __nv_bfloat16 *qh, *ql, *kvh, *kvl, *prh, *prl;
    cudaGetSymbolAddress((void**)&q,    g_q);
    cudaGetSymbolAddress((void**)&qabs, g_qabs);
    cudaGetSymbolAddress((void**)&sc,   g_scores);
    cudaGetSymbolAddress((void**)&ctx,  g_ctx);
    cudaGetSymbolAddress((void**)&part, g_ctx_part);
    cudaGetSymbolAddress((void**)&qh,   g_qabs_hi);
    cudaGetSymbolAddress((void**)&ql,   g_qabs_lo);
    cudaGetSymbolAddress((void**)&kvh,  g_kv_hi);
    cudaGetSymbolAddress((void**)&kvl,  g_kv_lo);
    cudaGetSymbolAddress((void**)&prh,  g_probs_hi);
    cudaGetSymbolAddress((void**)&prl,  g_probs_lo);

    cudaFuncSetAttribute(mma_bf16x3_kernel<false>,
                         cudaFuncAttributeMaxDynamicSharedMemorySize, MMA_SMEM);
    cudaFuncSetAttribute(mma_bf16x3_kernel<true>,
                         cudaFuncAttributeMaxDynamicSharedMemorySize, MMA_SMEM);

    // 0) kv -> hi/lo bf16 (elementwise; straight layout serves both MMA kernels)
    kv_split_kernel<<<(size_t)BATCH * LSEQ * RD / (8 * 256), 256>>>(
        (const float4*)kv, (uint4*)kvh, (uint4*)kvl);

    // 1) q = hs @ Wq^T + bq (fp32) — BN=64 for 256 CTAs
    gemm_kernel<32, 64, 32, 4, 4, true, true><<<dim3(HK / 64, 1), 128>>>(
        hs, Wq, bq, q, DQ, DQ, DQ, HK, 0, 0, 0);

    // 2) q_abs[b,h,r] = sum_k q[b,h,k] * w_kc[h,k,r] (fp32)
    gemm_kernel<32, 128, 16, 4, 8, false, false><<<dim3(RD / 128, HEADS), 128>>>(
        q, wkc, nullptr, qabs, KD, HK, RD, HEADS * RD,
        (long)KD, (long)KD * RD, (long)RD);

    // 2b) qabs -> hi/lo bf16
    split_kernel<<<(BATCH * HEADS * RD) / (4 * 256), 256>>>(
        (const float4*)qabs, (uint2*)qh, (uint2*)ql);

    // 3) scores = qabs @ kv^T via HMMA bf16x3 (B K-major): grid (l-tiles, batch)
    mma_bf16x3_kernel<false><<<dim3(LSEQ / 128, BATCH, 1), 256, MMA_SMEM>>>(
        qh, ql, kvh, kvl, sc, RD,
        (long)RD, (long)RD, (long)LSEQ,
        (long)HEADS * RD, (long)LSEQ * RD, (long)HEADS * LSEQ, 0);

    // 4) softmax -> probs hi/lo bf16
    softmax_split_kernel<<<BATCH * HEADS, 256>>>(sc, prh, prl);

    // 5) ctx = probs @ kv via HMMA bf16x3 (B N-major, trans ldmatrix), split-K x2
    mma_bf16x3_kernel<true><<<dim3(RD / 128, BATCH, 2), 256, MMA_SMEM>>>(
        prh, prl, kvh, kvl, part, LSEQ / 2,
        (long)LSEQ, (long)RD, (long)RD,
        (long)HEADS * LSEQ, (long)LSEQ * RD, (long)HEADS * RD,
        (long)BATCH * HEADS * RD);
    reduce_ctx<<<(BATCH * HEADS * RD) / (256 * 4), 256>>>(
        (const float4*)part, (const float4*)(part + BATCH * HEADS * RD), (float4*)ctx);

    // 6) out[b,h,k] = sum_r ctx[b,h,r] * w_vc[h,k,r] (fp32) — BN=64 for 256 CTAs
    gemm_kernel<32, 64, 16, 4, 4, true, false><<<dim3(KD / 64, HEADS), 128>>>(
        ctx, wvc, nullptr, out, RD, HEADS * RD, RD, HK,
        (long)RD, (long)KD * RD, (long)KD);
}